// round 1
// baseline (speedup 1.0000x reference)
#include <cuda_runtime.h>
#include <cstdint>

#define B 8
#define L 512
#define H 20
#define D 1280
#define K 32

// Scratch (no allocations allowed in kernel_launch)
__device__ float g_m[2][B][D];   // gather-means of selected rep rows, per rep/batch
__device__ float g_u[4][D];      // u1, u2 (cls), v1, v2 (env)

// ---------------------------------------------------------------------------
// Kernel 1: per (rep, batch) block — head-mean of attn[b,:,pos[b],:],
// bitonic top-K=32 selection, gather-mean of selected rep rows.
// ---------------------------------------------------------------------------
__global__ void __launch_bounds__(512) k_topk_mean(
    const float* __restrict__ rep1, const float* __restrict__ rep2,
    const float* __restrict__ attn1, const float* __restrict__ attn2,
    const int* __restrict__ pos)
{
    const int b = blockIdx.x;
    const int r = blockIdx.y;
    const float* rep  = r ? rep2  : rep1;
    const float* attn = r ? attn2 : attn1;
    const int l = threadIdx.x;               // 0..511, one token per thread
    const int p = pos[b];

    // w[l] = mean over H heads of attn[b,h,p,l]
    const float* base = attn + ((size_t)b * H) * (size_t)(L * L)
                             + (size_t)p * L + l;
    float s = 0.f;
#pragma unroll
    for (int h = 0; h < H; ++h)
        s += base[(size_t)h * (L * L)];
    const float w = s * (1.0f / H);

    // Order-preserving uint key; tie-break toward smaller index (like jax top_k)
    __shared__ unsigned long long key[L];
    unsigned fb = __float_as_uint(w);
    fb = (fb & 0x80000000u) ? ~fb : (fb | 0x80000000u);
    key[l] = ((unsigned long long)fb << 32) | (unsigned)(L - 1 - l);
    __syncthreads();

    // Bitonic sort, descending. 512 elements, 45 compare/sync stages.
    for (int kk = 2; kk <= L; kk <<= 1) {
        for (int j = kk >> 1; j > 0; j >>= 1) {
            int ixj = l ^ j;
            if (ixj > l) {
                bool up = ((l & kk) == 0);
                unsigned long long a = key[l], c = key[ixj];
                if (up ? (a < c) : (a > c)) { key[l] = c; key[ixj] = a; }
            }
            __syncthreads();
        }
    }

    __shared__ int idx[K];
    if (l < K) idx[l] = L - 1 - (int)(key[l] & 0xffffffffu);
    __syncthreads();

    // m[b,d] = mean over the K selected rows of rep[b, idx[k], d]
    const float* repb = rep + (size_t)b * L * D;
    for (int d = l; d < D; d += 512) {
        float acc = 0.f;
#pragma unroll
        for (int t = 0; t < K; ++t)
            acc += repb[(size_t)idx[t] * D + d];
        g_m[r][b][d] = acc * (1.0f / K);
    }
}

// ---------------------------------------------------------------------------
// Kernel 2: dual matvec. For each matrix (cls_W / env_W), each row i:
//   u1[i] = sum_j W[i,j] * (c1[j]*wclf[j]);  u2[i] same with c2.
// One warp per row; W read exactly once. This is the DRAM-bound kernel.
// ---------------------------------------------------------------------------
__global__ void __launch_bounds__(256) k_matvec(
    const float* __restrict__ cls_W, const float* __restrict__ env_W,
    const float* __restrict__ clsclf_W, const float* __restrict__ envclf_W,
    const float* __restrict__ cls_c1, const float* __restrict__ cls_c2,
    const float* __restrict__ env_c1, const float* __restrict__ env_c2)
{
    const int mat = blockIdx.y;   // 0 = cls, 1 = env
    const float* W  = mat ? env_W    : cls_W;
    const float* wc = mat ? envclf_W : clsclf_W;
    const float* c1 = mat ? env_c1   : cls_c1;
    const float* c2 = mat ? env_c2   : cls_c2;

    const int warp = threadIdx.x >> 5;
    const int lane = threadIdx.x & 31;
    const int row  = blockIdx.x * 8 + warp;
    const float* Wr = W + (size_t)row * D;

    float a1 = 0.f, a2 = 0.f;
    // D=1280: 10 float4 iterations per lane
    for (int j = lane * 4; j < D; j += 128) {
        float4 wv  = *(const float4*)(Wr + j);
        float4 wcv = *(const float4*)(wc + j);
        float4 c1v = *(const float4*)(c1 + j);
        float4 c2v = *(const float4*)(c2 + j);
        float sx = wv.x * wcv.x, sy = wv.y * wcv.y,
              sz = wv.z * wcv.z, sw = wv.w * wcv.w;
        a1 += sx * c1v.x + sy * c1v.y + sz * c1v.z + sw * c1v.w;
        a2 += sx * c2v.x + sy * c2v.y + sz * c2v.z + sw * c2v.w;
    }
#pragma unroll
    for (int o = 16; o; o >>= 1) {
        a1 += __shfl_xor_sync(0xffffffffu, a1, o);
        a2 += __shfl_xor_sync(0xffffffffu, a2, o);
    }
    if (lane == 0) {
        g_u[mat * 2 + 0][row] = a1;
        g_u[mat * 2 + 1][row] = a2;
    }
}

// ---------------------------------------------------------------------------
// Kernel 3: final per-batch scalar:
// out[b] = ( rep1[b,0]·u1 + rep2[b,0]·u2 + m1[b]·v1 + m2[b]·v2
//          + sum_d cls_b[d]*(cls_c1+cls_c2)[d]*clsclf_W[d]
//          + sum_d env_b[d]*(env_c1+env_c2)[d]*envclf_W[d]
//          + clsclf_b + envclf_b ) / 2
// ---------------------------------------------------------------------------
__global__ void __launch_bounds__(256) k_final(
    const float* __restrict__ rep1, const float* __restrict__ rep2,
    const float* __restrict__ cls_b, const float* __restrict__ env_b,
    const float* __restrict__ clsclf_W, const float* __restrict__ envclf_W,
    const float* __restrict__ clsclf_b, const float* __restrict__ envclf_b,
    const float* __restrict__ cls_c1, const float* __restrict__ cls_c2,
    const float* __restrict__ env_c1, const float* __restrict__ env_c2,
    float* __restrict__ out)
{
    const int b = blockIdx.x;
    const float* r1 = rep1 + (size_t)b * L * D;   // token 0 row
    const float* r2 = rep2 + (size_t)b * L * D;

    float acc = 0.f;
    for (int d = threadIdx.x; d < D; d += 256) {
        acc += r1[d] * g_u[0][d] + r2[d] * g_u[1][d]
             + g_m[0][b][d] * g_u[2][d] + g_m[1][b][d] * g_u[3][d]
             + cls_b[d] * (cls_c1[d] + cls_c2[d]) * clsclf_W[d]
             + env_b[d] * (env_c1[d] + env_c2[d]) * envclf_W[d];
    }

    // block reduce (8 warps)
    __shared__ float red[8];
#pragma unroll
    for (int o = 16; o; o >>= 1) acc += __shfl_xor_sync(0xffffffffu, acc, o);
    if ((threadIdx.x & 31) == 0) red[threadIdx.x >> 5] = acc;
    __syncthreads();
    if (threadIdx.x == 0) {
        float t = 0.f;
#pragma unroll
        for (int w = 0; w < 8; ++w) t += red[w];
        out[b] = (t + clsclf_b[0] + envclf_b[0]) * 0.5f;
    }
}

// ---------------------------------------------------------------------------
extern "C" void kernel_launch(void* const* d_in, const int* in_sizes, int n_in,
                              void* d_out, int out_size)
{
    const float* rep1     = (const float*)d_in[0];
    const float* rep2     = (const float*)d_in[1];
    const float* attn1    = (const float*)d_in[2];
    const float* attn2    = (const float*)d_in[3];
    const int*   pos      = (const int*)  d_in[4];
    const float* cls_W    = (const float*)d_in[5];
    const float* cls_b    = (const float*)d_in[6];
    const float* env_W    = (const float*)d_in[7];
    const float* env_b    = (const float*)d_in[8];
    const float* clsclf_W = (const float*)d_in[9];
    const float* clsclf_b = (const float*)d_in[10];
    const float* envclf_W = (const float*)d_in[11];
    const float* envclf_b = (const float*)d_in[12];
    const float* cls_c1   = (const float*)d_in[13];
    const float* cls_c2   = (const float*)d_in[14];
    const float* env_c1   = (const float*)d_in[15];
    const float* env_c2   = (const float*)d_in[16];
    float* out = (float*)d_out;

    dim3 g1(B, 2);
    k_topk_mean<<<g1, 512>>>(rep1, rep2, attn1, attn2, pos);

    dim3 g2(D / 8, 2);
    k_matvec<<<g2, 256>>>(cls_W, env_W, clsclf_W, envclf_W,
                          cls_c1, cls_c2, env_c1, env_c2);

    k_final<<<B, 256>>>(rep1, rep2, cls_b, env_b,
                        clsclf_W, envclf_W, clsclf_b, envclf_b,
                        cls_c1, cls_c2, env_c1, env_c2, out);
}